// round 5
// baseline (speedup 1.0000x reference)
#include <cuda_runtime.h>
#include <math.h>

#define BB  4
#define NN  20000
#define EE  640000
#define FF  64
#define EDD 16
#define D1  128
#define HIDC 16

typedef unsigned long long ull;

__device__ __forceinline__ ull fma2(ull a, ull b, ull c) {
    ull d; asm("fma.rn.f32x2 %0, %1, %2, %3;" : "=l"(d) : "l"(a), "l"(b), "l"(c)); return d;
}
__device__ __forceinline__ ull add2(ull a, ull b) {
    ull d; asm("add.rn.f32x2 %0, %1, %2;" : "=l"(d) : "l"(a), "l"(b)); return d;
}
union F4U { float4 f; ulonglong2 u; };

// ---------------- device scratch ----------------
__device__ int   g_count [BB*NN];
__device__ int   g_cursor[BB*NN];
__device__ int   g_offsets[BB*(NN+1)];
__device__ int   g_elist [BB*EE];
__device__ int   g_slist [BB*EE];
__device__ float g_xl1[BB*NN*D1];
__device__ float g_xr1[BB*NN*D1];
__device__ float g_hx [BB*NN*D1];
__device__ float g_hs [BB*NN*D1];
__device__ float g_xl2[BB*NN*HIDC];
__device__ float g_xr2[BB*NN*HIDC];
__device__ float g_xls[BB*NN*HIDC];
__device__ float g_xrs[BB*NN*HIDC];

// ---------------- CSR build ----------------
__global__ void zero_kernel() {
    int i = blockIdx.x * blockDim.x + threadIdx.x;
    if (i < BB*NN) { g_count[i] = 0; g_cursor[i] = 0; }
}

__global__ void count_kernel(const int* __restrict__ ei) {
    int i = blockIdx.x * blockDim.x + threadIdx.x;
    if (i >= BB*EE) return;
    int b = i / EE, e = i - b*EE;
    int dst = ei[b*2*EE + EE + e];
    atomicAdd(&g_count[b*NN + dst], 1);
}

__global__ void scan_kernel() {
    __shared__ int sh[1024];
    int b = blockIdx.x, tid = threadIdx.x;
    int running = 0;
    for (int base = 0; base < NN; base += 1024) {
        int i = base + tid;
        int v = (i < NN) ? g_count[b*NN + i] : 0;
        __syncthreads();
        sh[tid] = v; __syncthreads();
        #pragma unroll
        for (int off = 1; off < 1024; off <<= 1) {
            int t = (tid >= off) ? sh[tid - off] : 0;
            __syncthreads();
            sh[tid] += t;
            __syncthreads();
        }
        if (i < NN) g_offsets[b*(NN+1) + i] = running + sh[tid] - v;
        running += sh[1023];
    }
    if (tid == 0) g_offsets[b*(NN+1) + NN] = running;
}

__global__ void scatter_kernel(const int* __restrict__ ei) {
    int i = blockIdx.x * blockDim.x + threadIdx.x;
    if (i >= BB*EE) return;
    int b = i / EE, e = i - b*EE;
    int src = ei[b*2*EE + e];
    int dst = ei[b*2*EE + EE + e];
    int pos = atomicAdd(&g_cursor[b*NN + dst], 1);
    int slot = b*EE + g_offsets[b*(NN+1) + dst] + pos;
    g_elist[slot] = e;
    g_slist[slot] = src;
}

// ---------------- GEMM 1: xl1 = x@Wl1, xr1 = x@Wr1 ----------------
__global__ void __launch_bounds__(256) gemm1_kernel(const float* __restrict__ x,
                                                    const float* __restrict__ Wl,
                                                    const float* __restrict__ Wr) {
    __shared__ float sX[64*64];
    __shared__ float sW[64*128];
    int b = blockIdx.y, n0 = blockIdx.x * 64, tid = threadIdx.x;

    for (int t = tid; t < 64*64; t += 256) {
        int r = t >> 6, c = t & 63;
        int n = n0 + r;
        sX[t] = (n < NN) ? x[(b*NN + n)*FF + c] : 0.f;
    }
    int ty = tid >> 4, tx = tid & 15;
    for (int pass = 0; pass < 2; ++pass) {
        const float* W = pass ? Wr : Wl;
        __syncthreads();
        for (int t = tid; t < 64*128; t += 256) sW[t] = W[t];
        __syncthreads();
        float acc[4][8];
        #pragma unroll
        for (int i = 0; i < 4; i++)
            #pragma unroll
            for (int j = 0; j < 8; j++) acc[i][j] = 0.f;
        for (int k = 0; k < 64; k++) {
            float a[4], bb[8];
            #pragma unroll
            for (int i = 0; i < 4; i++) a[i] = sX[(ty*4 + i)*64 + k];
            #pragma unroll
            for (int j = 0; j < 8; j++) bb[j] = sW[k*128 + tx*8 + j];
            #pragma unroll
            for (int i = 0; i < 4; i++)
                #pragma unroll
                for (int j = 0; j < 8; j++) acc[i][j] = fmaf(a[i], bb[j], acc[i][j]);
        }
        float* out = pass ? g_xr1 : g_xl1;
        #pragma unroll
        for (int i = 0; i < 4; i++) {
            int n = n0 + ty*4 + i;
            if (n < NN) {
                #pragma unroll
                for (int j = 0; j < 8; j++)
                    out[(b*NN + n)*128 + tx*8 + j] = acc[i][j];
            }
        }
    }
}

// ------- conv1: warp/node, f32x2 ee via per-warp smem dup buffer -------
__global__ void __launch_bounds__(256) conv1_kernel(const float* __restrict__ ea,
                                                    const float* __restrict__ We,
                                                    const float* __restrict__ att,
                                                    const float* __restrict__ bias) {
    __shared__ float2 sdup[8][2][16];
    int b = blockIdx.y;
    int w = threadIdx.x >> 5;
    int n = blockIdx.x * 8 + w;
    if (n >= NN) return;
    int lane = threadIdx.x & 31;
    int cb = 4 * lane;
    int lx = lane & 15;
    int row = b*NN + n;

    F4U xr; xr.f = *(const float4*)(g_xr1 + (size_t)row*128 + cb);
    float4 at4 = *(const float4*)(att + cb);
    ull WeA[16], WeB[16];
    #pragma unroll
    for (int k = 0; k < 16; k++) {
        F4U t; t.f = *(const float4*)(We + k*128 + cb);
        WeA[k] = t.u.x; WeB[k] = t.u.y;
    }

    const int*   elist = g_elist + b*EE;
    const int*   slist = g_slist + b*EE;
    const float* eab   = ea + (size_t)b*EE*EDD;
    int start = g_offsets[b*(NN+1) + n];
    int end   = g_offsets[b*(NN+1) + n + 1];

    float acc0 = 0.f, acc1 = 0.f, acc2 = 0.f, acc3 = 0.f, den = 0.f;

    F4U xlCur; xlCur.f = make_float4(0.f,0.f,0.f,0.f);
    float aCur = 0.f;
    int eN = 0, sN = 0;
    if (start < end) {
        int e0 = elist[start], s0 = slist[start];
        aCur = eab[(size_t)e0*EDD + lx];
        xlCur.f = *(const float4*)(g_xl1 + (size_t)(b*NN + s0)*128 + cb);
    }
    if (start + 1 < end) { eN = elist[start+1]; sN = slist[start+1]; }

    for (int i = start; i < end; i++) {
        int buf = i & 1;
        if (lane < 16) sdup[w][buf][lx] = make_float2(aCur, aCur);
        F4U xl = xlCur;
        __syncwarp();
        if (i + 1 < end) {
            aCur = eab[(size_t)eN*EDD + lx];
            xlCur.f = *(const float4*)(g_xl1 + (size_t)(b*NN + sN)*128 + cb);
        }
        if (i + 2 < end) { eN = elist[i+2]; sN = slist[i+2]; }

        ull uA = add2(xl.u.x, xr.u.x);
        ull uB = add2(xl.u.y, xr.u.y);
        #pragma unroll
        for (int k = 0; k < 16; k++) {
            ull a2 = *(const ull*)&sdup[w][buf][k];
            uA = fma2(a2, WeA[k], uA);
            uB = fma2(a2, WeB[k], uB);
        }
        F4U uu; uu.u.x = uA; uu.u.y = uB;
        float u0 = uu.f.x, u1 = uu.f.y, u2 = uu.f.z, u3 = uu.f.w;
        u0 = fmaxf(u0, 0.f) + 0.2f * fminf(u0, 0.f);
        u1 = fmaxf(u1, 0.f) + 0.2f * fminf(u1, 0.f);
        u2 = fmaxf(u2, 0.f) + 0.2f * fminf(u2, 0.f);
        u3 = fmaxf(u3, 0.f) + 0.2f * fminf(u3, 0.f);
        float s = fmaf(u0, at4.x, fmaf(u1, at4.y, fmaf(u2, at4.z, u3 * at4.w)));
        s += __shfl_xor_sync(0xffffffffu, s, 1);
        s += __shfl_xor_sync(0xffffffffu, s, 2);
        float exs = __expf(s);
        den += exs;
        acc0 = fmaf(xl.f.x, exs, acc0);
        acc1 = fmaf(xl.f.y, exs, acc1);
        acc2 = fmaf(xl.f.z, exs, acc2);
        acc3 = fmaf(xl.f.w, exs, acc3);
    }

    float inv = 1.f / (den + 1e-16f);
    float4 b4 = *(const float4*)(bias + cb);
    float h0 = fmaf(acc0, inv, b4.x);
    float h1 = fmaf(acc1, inv, b4.y);
    float h2 = fmaf(acc2, inv, b4.z);
    float h3 = fmaf(acc3, inv, b4.w);
    float o0 = h0 > 0.f ? h0 : expm1f(h0);
    float o1 = h1 > 0.f ? h1 : expm1f(h1);
    float o2 = h2 > 0.f ? h2 : expm1f(h2);
    float o3 = h3 > 0.f ? h3 : expm1f(h3);
    float4 sk = *(const float4*)(g_xl1 + (size_t)row*128 + cb);
    *(float4*)(g_hx + (size_t)row*128 + cb) = make_float4(o0, o1, o2, o3);
    *(float4*)(g_hs + (size_t)row*128 + cb) = make_float4(o0 + sk.x, o1 + sk.y, o2 + sk.z, o3 + sk.w);
}

// ---------------- GEMM 2: four [N,128]@[128,16] projections ----------------
__global__ void __launch_bounds__(256) gemm2_kernel(const float* __restrict__ c2Wl,
                                                    const float* __restrict__ c2Wr,
                                                    const float* __restrict__ sWl,
                                                    const float* __restrict__ sWr) {
    __shared__ float sT[64*128];
    __shared__ float sW[128*32];
    int b = blockIdx.y, n0 = blockIdx.x * 64, tid = threadIdx.x;
    int ty = tid >> 3, tx = tid & 7;

    for (int pass = 0; pass < 2; ++pass) {
        const float* inp = pass ? g_hs : g_hx;
        const float* Wl  = pass ? sWl  : c2Wl;
        const float* Wr  = pass ? sWr  : c2Wr;
        __syncthreads();
        for (int t = tid; t < 64*128; t += 256) {
            int r = t >> 7, c = t & 127;
            int n = n0 + r;
            sT[t] = (n < NN) ? inp[(b*NN + n)*128 + c] : 0.f;
        }
        for (int t = tid; t < 128*16; t += 256) {
            int r = t >> 4, c = t & 15;
            sW[r*32 + c]      = Wl[t];
            sW[r*32 + 16 + c] = Wr[t];
        }
        __syncthreads();
        float acc[2][4] = {{0.f,0.f,0.f,0.f},{0.f,0.f,0.f,0.f}};
        for (int k = 0; k < 128; k++) {
            float a0 = sT[(ty*2)*128 + k];
            float a1 = sT[(ty*2 + 1)*128 + k];
            float bb[4];
            #pragma unroll
            for (int j = 0; j < 4; j++) bb[j] = sW[k*32 + tx*4 + j];
            #pragma unroll
            for (int j = 0; j < 4; j++) {
                acc[0][j] = fmaf(a0, bb[j], acc[0][j]);
                acc[1][j] = fmaf(a1, bb[j], acc[1][j]);
            }
        }
        float* outl = pass ? g_xls : g_xl2;
        float* outr = pass ? g_xrs : g_xr2;
        #pragma unroll
        for (int i = 0; i < 2; i++) {
            int n = n0 + ty*2 + i;
            if (n < NN) {
                #pragma unroll
                for (int j = 0; j < 4; j++) {
                    int c = tx*4 + j;
                    if (c < 16) outl[(b*NN + n)*16 + c]      = acc[i][j];
                    else        outr[(b*NN + n)*16 + c - 16] = acc[i][j];
                }
            }
        }
    }
}

// ------- conv2 + skip + lin + layernorm fused; ea via uniform LDG.128 -------
__global__ void __launch_bounds__(256) conv2_kernel(const float* __restrict__ ea,
                                                    const float* __restrict__ c2We,
                                                    const float* __restrict__ c2att,
                                                    const float* __restrict__ c2b,
                                                    const float* __restrict__ sWe,
                                                    const float* __restrict__ satt,
                                                    const float* __restrict__ sb,
                                                    const float* __restrict__ linW,
                                                    const float* __restrict__ linb,
                                                    const float* __restrict__ lng,
                                                    const float* __restrict__ lnb,
                                                    float* __restrict__ out) {
    int b = blockIdx.y;
    int n = blockIdx.x * 8 + (threadIdx.x >> 5);
    if (n >= NN) return;
    int lane = threadIdx.x & 31;
    int half = lane >> 4;
    int c = lane & 15;

    const float* xlbase = half ? g_xls : g_xl2;
    float xr   = (half ? g_xrs : g_xr2)[(size_t)(b*NN + n)*16 + c];
    float attv = (half ? satt : c2att)[c];
    float Wc[16];
    const float* Wmat = half ? sWe : c2We;
    #pragma unroll
    for (int k = 0; k < 16; k++) Wc[k] = Wmat[k*16 + c];

    const int*   elist = g_elist + b*EE;
    const int*   slist = g_slist + b*EE;
    const float* eab   = ea + (size_t)b*EE*EDD;
    int start = g_offsets[b*(NN+1) + n];
    int end   = g_offsets[b*(NN+1) + n + 1];

    float acc = 0.f, den = 0.f;
    float xlCur = 0.f;
    float4 eaCur[4];
    int eN = 0, sN = 0;
    if (start < end) {
        int e0 = elist[start], s0 = slist[start];
        xlCur = xlbase[(size_t)(b*NN + s0)*16 + c];
        const float4* p = (const float4*)(eab + (size_t)e0*EDD);
        eaCur[0] = p[0]; eaCur[1] = p[1]; eaCur[2] = p[2]; eaCur[3] = p[3];
    }
    if (start + 1 < end) { eN = elist[start+1]; sN = slist[start+1]; }

    for (int i = start; i < end; i++) {
        float xl = xlCur;
        float av[16];
        #pragma unroll
        for (int q = 0; q < 4; q++) {
            av[4*q+0] = eaCur[q].x; av[4*q+1] = eaCur[q].y;
            av[4*q+2] = eaCur[q].z; av[4*q+3] = eaCur[q].w;
        }
        if (i + 1 < end) {
            xlCur = xlbase[(size_t)(b*NN + sN)*16 + c];
            const float4* p = (const float4*)(eab + (size_t)eN*EDD);
            eaCur[0] = p[0]; eaCur[1] = p[1]; eaCur[2] = p[2]; eaCur[3] = p[3];
        }
        if (i + 2 < end) { eN = elist[i+2]; sN = slist[i+2]; }

        float u = xl + xr;
        #pragma unroll
        for (int k = 0; k < 16; k++) u = fmaf(av[k], Wc[k], u);
        u = fmaxf(u, 0.f) + 0.2f * fminf(u, 0.f);
        float s = u * attv;
        s += __shfl_xor_sync(0xffffffffu, s, 1);
        s += __shfl_xor_sync(0xffffffffu, s, 2);
        s += __shfl_xor_sync(0xffffffffu, s, 4);
        s += __shfl_xor_sync(0xffffffffu, s, 8);
        float exs = __expf(s);
        den += exs;
        acc = fmaf(xl, exs, acc);
    }

    float v = acc / (den + 1e-16f) + (half ? sb[c] : c2b[c]);

    float t = 0.f;
    #pragma unroll
    for (int k = 0; k < 16; k++) {
        float vk = __shfl_sync(0xffffffffu, v, k, 16);
        t = fmaf(vk, linW[c*16 + k], t);
    }
    float part  = half ? (t + linb[c]) : v;
    float other = __shfl_xor_sync(0xffffffffu, part, 16);
    float y = part + other;

    float mu = y;
    mu += __shfl_xor_sync(0xffffffffu, mu, 1);
    mu += __shfl_xor_sync(0xffffffffu, mu, 2);
    mu += __shfl_xor_sync(0xffffffffu, mu, 4);
    mu += __shfl_xor_sync(0xffffffffu, mu, 8);
    mu *= (1.f / 16.f);
    float d = y - mu;
    float var = d * d;
    var += __shfl_xor_sync(0xffffffffu, var, 1);
    var += __shfl_xor_sync(0xffffffffu, var, 2);
    var += __shfl_xor_sync(0xffffffffu, var, 4);
    var += __shfl_xor_sync(0xffffffffu, var, 8);
    var *= (1.f / 16.f);
    float o = d * rsqrtf(var + 1e-5f) * lng[c] + lnb[c];
    if (!half) out[(size_t)(b*NN + n)*16 + c] = o;
}

// ---------------- launch ----------------
extern "C" void kernel_launch(void* const* d_in, const int* in_sizes, int n_in,
                              void* d_out, int out_size) {
    const float* x      = (const float*)d_in[0];
    const float* ea     = (const float*)d_in[1];
    const int*   ei     = (const int*)  d_in[2];
    const float* c1_Wl  = (const float*)d_in[3];
    const float* c1_Wr  = (const float*)d_in[4];
    const float* c1_We  = (const float*)d_in[5];
    const float* c1_att = (const float*)d_in[6];
    const float* c1_b   = (const float*)d_in[7];
    const float* c2_Wl  = (const float*)d_in[8];
    const float* c2_Wr  = (const float*)d_in[9];
    const float* c2_We  = (const float*)d_in[10];
    const float* c2_att = (const float*)d_in[11];
    const float* c2_b   = (const float*)d_in[12];
    const float* s_Wl   = (const float*)d_in[13];
    const float* s_Wr   = (const float*)d_in[14];
    const float* s_We   = (const float*)d_in[15];
    const float* s_att  = (const float*)d_in[16];
    const float* s_b    = (const float*)d_in[17];
    const float* lin_W  = (const float*)d_in[18];
    const float* lin_b  = (const float*)d_in[19];
    const float* ln_g   = (const float*)d_in[20];
    const float* ln_b   = (const float*)d_in[21];
    float* out = (float*)d_out;

    zero_kernel   <<<(BB*NN + 255)/256, 256>>>();
    count_kernel  <<<(BB*EE + 255)/256, 256>>>(ei);
    scan_kernel   <<<BB, 1024>>>();
    scatter_kernel<<<(BB*EE + 255)/256, 256>>>(ei);

    gemm1_kernel<<<dim3((NN + 63)/64, BB), 256>>>(x, c1_Wl, c1_Wr);
    conv1_kernel<<<dim3((NN + 7)/8,  BB), 256>>>(ea, c1_We, c1_att, c1_b);
    gemm2_kernel<<<dim3((NN + 63)/64, BB), 256>>>(c2_Wl, c2_Wr, s_Wl, s_Wr);
    conv2_kernel<<<dim3((NN + 7)/8,  BB), 256>>>(ea, c2_We, c2_att, c2_b,
                                                 s_We, s_att, s_b,
                                                 lin_W, lin_b, ln_g, ln_b, out);
}

// round 7
// speedup vs baseline: 1.7791x; 1.7791x over previous
#include <cuda_runtime.h>
#include <math.h>

#define BB  4
#define NN  20000
#define EE  640000
#define FF  64
#define EDD 16
#define D1  128
#define HIDC 16

// ---------------- device scratch (no cudaMalloc allowed) ----------------
__device__ int   g_count [BB*NN];
__device__ int   g_cursor[BB*NN];
__device__ int   g_offsets[BB*(NN+1)];
__device__ int   g_elist [BB*EE];
__device__ int   g_slist [BB*EE];
__device__ float g_xl1[BB*NN*D1];
__device__ float g_xr1[BB*NN*D1];
__device__ float g_hx [BB*NN*D1];
__device__ float g_hs [BB*NN*D1];
__device__ float g_xl2[BB*NN*HIDC];
__device__ float g_xr2[BB*NN*HIDC];
__device__ float g_xls[BB*NN*HIDC];
__device__ float g_xrs[BB*NN*HIDC];

// ---------------- CSR build ----------------
__global__ void zero_kernel() {
    int i = blockIdx.x * blockDim.x + threadIdx.x;
    if (i < BB*NN) { g_count[i] = 0; g_cursor[i] = 0; }
}

__global__ void count_kernel(const int* __restrict__ ei) {
    int i = blockIdx.x * blockDim.x + threadIdx.x;
    if (i >= BB*EE) return;
    int b = i / EE, e = i - b*EE;
    int dst = ei[b*2*EE + EE + e];
    atomicAdd(&g_count[b*NN + dst], 1);
}

// warp-scan based block scan: 3 barriers per 1024-chunk
__global__ void scan_kernel() {
    __shared__ int warpsum[32];
    __shared__ int chunkoff;
    int b = blockIdx.x, tid = threadIdx.x;
    int lane = tid & 31, wid = tid >> 5;
    if (tid == 0) chunkoff = 0;
    __syncthreads();
    for (int base = 0; base < NN; base += 1024) {
        int i = base + tid;
        int v = (i < NN) ? g_count[b*NN + i] : 0;
        int s = v;
        #pragma unroll
        for (int off = 1; off < 32; off <<= 1) {
            int t = __shfl_up_sync(0xffffffffu, s, off);
            if (lane >= off) s += t;
        }
        if (lane == 31) warpsum[wid] = s;
        __syncthreads();
        if (wid == 0) {
            int ws = warpsum[lane];
            #pragma unroll
            for (int off = 1; off < 32; off <<= 1) {
                int t = __shfl_up_sync(0xffffffffu, ws, off);
                if (lane >= off) ws += t;
            }
            warpsum[lane] = ws;
        }
        __syncthreads();
        int prefix = chunkoff + (wid > 0 ? warpsum[wid-1] : 0) + s - v;  // exclusive
        if (i < NN) g_offsets[b*(NN+1) + i] = prefix;
        __syncthreads();
        if (tid == 0) chunkoff += warpsum[31];
        __syncthreads();
    }
    if (threadIdx.x == 0) g_offsets[b*(NN+1) + NN] = chunkoff;
}

__global__ void scatter_kernel(const int* __restrict__ ei) {
    int i = blockIdx.x * blockDim.x + threadIdx.x;
    if (i >= BB*EE) return;
    int b = i / EE, e = i - b*EE;
    int src = ei[b*2*EE + e];
    int dst = ei[b*2*EE + EE + e];
    int pos = atomicAdd(&g_cursor[b*NN + dst], 1);
    int slot = b*EE + g_offsets[b*(NN+1) + dst] + pos;
    g_elist[slot] = e;
    g_slist[slot] = src;
}

// ---------------- GEMM 1: xl1 = x@Wl1, xr1 = x@Wr1 ----------------
__global__ void __launch_bounds__(256) gemm1_kernel(const float* __restrict__ x,
                                                    const float* __restrict__ Wl,
                                                    const float* __restrict__ Wr) {
    __shared__ float sX[64*64];
    __shared__ float sW[64*128];
    int b = blockIdx.y, n0 = blockIdx.x * 64, tid = threadIdx.x;

    for (int t = tid; t < 64*64; t += 256) {
        int r = t >> 6, c = t & 63;
        int n = n0 + r;
        sX[t] = (n < NN) ? x[(b*NN + n)*FF + c] : 0.f;
    }
    int ty = tid >> 4, tx = tid & 15;
    for (int pass = 0; pass < 2; ++pass) {
        const float* W = pass ? Wr : Wl;
        __syncthreads();
        for (int t = tid; t < 64*128; t += 256) sW[t] = W[t];
        __syncthreads();
        float acc[4][8];
        #pragma unroll
        for (int i = 0; i < 4; i++)
            #pragma unroll
            for (int j = 0; j < 8; j++) acc[i][j] = 0.f;
        for (int k = 0; k < 64; k += 4) {
            float4 a4[4];
            #pragma unroll
            for (int i = 0; i < 4; i++)
                a4[i] = *(const float4*)&sX[(ty*4 + i)*64 + k];
            #pragma unroll
            for (int kk = 0; kk < 4; kk++) {
                float bb[8];
                #pragma unroll
                for (int j = 0; j < 8; j++) bb[j] = sW[(k+kk)*128 + tx*8 + j];
                #pragma unroll
                for (int i = 0; i < 4; i++) {
                    float a = (kk == 0) ? a4[i].x : (kk == 1) ? a4[i].y : (kk == 2) ? a4[i].z : a4[i].w;
                    #pragma unroll
                    for (int j = 0; j < 8; j++) acc[i][j] = fmaf(a, bb[j], acc[i][j]);
                }
            }
        }
        float* out = pass ? g_xr1 : g_xl1;
        #pragma unroll
        for (int i = 0; i < 4; i++) {
            int n = n0 + ty*4 + i;
            if (n < NN) {
                #pragma unroll
                for (int j = 0; j < 8; j++)
                    out[(b*NN + n)*128 + tx*8 + j] = acc[i][j];
            }
        }
    }
}

// ------- conv1: warp per node, depth-2 software pipeline over edges -------
__global__ void __launch_bounds__(256, 2) conv1_kernel(const float* __restrict__ ea,
                                                       const float* __restrict__ We,
                                                       const float* __restrict__ att,
                                                       const float* __restrict__ bias) {
    int b = blockIdx.y;
    int n = blockIdx.x * 8 + (threadIdx.x >> 5);
    if (n >= NN) return;
    int lane = threadIdx.x & 31;
    int cb = 4 * lane;
    int lx = lane & 15;
    int row = b*NN + n;

    float4 xr4 = *(const float4*)(g_xr1 + (size_t)row*128 + cb);
    float4 at4 = *(const float4*)(att + cb);
    float4 We4[16];
    #pragma unroll
    for (int k = 0; k < 16; k++) We4[k] = *(const float4*)(We + k*128 + cb);

    const int*   elist = g_elist + b*EE;
    const int*   slist = g_slist + b*EE;
    const float* eab   = ea + (size_t)b*EE*EDD;
    int start = g_offsets[b*(NN+1) + n];
    int end   = g_offsets[b*(NN+1) + n + 1];

    float acc0 = 0.f, acc1 = 0.f, acc2 = 0.f, acc3 = 0.f, den = 0.f;

    auto body = [&](float4 xl, float eav) {
        float u0 = xl.x + xr4.x, u1 = xl.y + xr4.y, u2 = xl.z + xr4.z, u3 = xl.w + xr4.w;
        #pragma unroll
        for (int k = 0; k < 16; k++) {
            float a = __shfl_sync(0xffffffffu, eav, k, 16);
            u0 = fmaf(a, We4[k].x, u0);
            u1 = fmaf(a, We4[k].y, u1);
            u2 = fmaf(a, We4[k].z, u2);
            u3 = fmaf(a, We4[k].w, u3);
        }
        u0 = fmaxf(u0, 0.f) + 0.2f * fminf(u0, 0.f);
        u1 = fmaxf(u1, 0.f) + 0.2f * fminf(u1, 0.f);
        u2 = fmaxf(u2, 0.f) + 0.2f * fminf(u2, 0.f);
        u3 = fmaxf(u3, 0.f) + 0.2f * fminf(u3, 0.f);
        float s = fmaf(u0, at4.x, fmaf(u1, at4.y, fmaf(u2, at4.z, u3 * at4.w)));
        s += __shfl_xor_sync(0xffffffffu, s, 1);
        s += __shfl_xor_sync(0xffffffffu, s, 2);
        float exs = __expf(s);
        den += exs;
        acc0 = fmaf(xl.x, exs, acc0);
        acc1 = fmaf(xl.y, exs, acc1);
        acc2 = fmaf(xl.z, exs, acc2);
        acc3 = fmaf(xl.w, exs, acc3);
    };

    // depth-2 pipeline: data for i,i+1 resident; indices for i+2,i+3 resident
    float4 xl0 = make_float4(0.f,0.f,0.f,0.f), xl1 = xl0;
    float  ea0 = 0.f, ea1 = 0.f;
    int e2 = 0, s2 = 0, e3 = 0, s3 = 0;
    if (start < end) {
        int e = elist[start], s = slist[start];
        ea0 = eab[(size_t)e*EDD + lx];
        xl0 = *(const float4*)(g_xl1 + (size_t)(b*NN + s)*128 + cb);
    }
    if (start + 1 < end) {
        int e = elist[start+1], s = slist[start+1];
        ea1 = eab[(size_t)e*EDD + lx];
        xl1 = *(const float4*)(g_xl1 + (size_t)(b*NN + s)*128 + cb);
    }
    if (start + 2 < end) { e2 = elist[start+2]; s2 = slist[start+2]; }
    if (start + 3 < end) { e3 = elist[start+3]; s3 = slist[start+3]; }

    for (int i = start; i < end; i += 2) {
        float4 xlc = xl0; float eac = ea0;
        if (i + 2 < end) {
            ea0 = eab[(size_t)e2*EDD + lx];
            xl0 = *(const float4*)(g_xl1 + (size_t)(b*NN + s2)*128 + cb);
        }
        if (i + 4 < end) { e2 = elist[i+4]; s2 = slist[i+4]; }
        body(xlc, eac);
        if (i + 1 < end) {
            float4 xld = xl1; float ead = ea1;
            if (i + 3 < end) {
                ea1 = eab[(size_t)e3*EDD + lx];
                xl1 = *(const float4*)(g_xl1 + (size_t)(b*NN + s3)*128 + cb);
            }
            if (i + 5 < end) { e3 = elist[i+5]; s3 = slist[i+5]; }
            body(xld, ead);
        }
    }

    float inv = 1.f / (den + 1e-16f);
    float4 b4 = *(const float4*)(bias + cb);
    float h0 = fmaf(acc0, inv, b4.x);
    float h1 = fmaf(acc1, inv, b4.y);
    float h2 = fmaf(acc2, inv, b4.z);
    float h3 = fmaf(acc3, inv, b4.w);
    float o0 = h0 > 0.f ? h0 : expm1f(h0);
    float o1 = h1 > 0.f ? h1 : expm1f(h1);
    float o2 = h2 > 0.f ? h2 : expm1f(h2);
    float o3 = h3 > 0.f ? h3 : expm1f(h3);
    float4 sk = *(const float4*)(g_xl1 + (size_t)row*128 + cb);
    *(float4*)(g_hx + (size_t)row*128 + cb) = make_float4(o0, o1, o2, o3);
    *(float4*)(g_hs + (size_t)row*128 + cb) = make_float4(o0 + sk.x, o1 + sk.y, o2 + sk.z, o3 + sk.w);
}

// ---------------- GEMM 2: four [N,128]@[128,16] projections ----------------
__global__ void __launch_bounds__(256) gemm2_kernel(const float* __restrict__ c2Wl,
                                                    const float* __restrict__ c2Wr,
                                                    const float* __restrict__ sWl,
                                                    const float* __restrict__ sWr) {
    __shared__ float sT[64*128];
    __shared__ float sW[128*32];
    int b = blockIdx.y, n0 = blockIdx.x * 64, tid = threadIdx.x;
    int ty = tid >> 3, tx = tid & 7;

    for (int pass = 0; pass < 2; ++pass) {
        const float* inp = pass ? g_hs : g_hx;
        const float* Wl  = pass ? sWl  : c2Wl;
        const float* Wr  = pass ? sWr  : c2Wr;
        __syncthreads();
        for (int t = tid; t < 64*128; t += 256) {
            int r = t >> 7, c = t & 127;
            int n = n0 + r;
            sT[t] = (n < NN) ? inp[(b*NN + n)*128 + c] : 0.f;
        }
        for (int t = tid; t < 128*16; t += 256) {
            int r = t >> 4, c = t & 15;
            sW[r*32 + c]      = Wl[t];
            sW[r*32 + 16 + c] = Wr[t];
        }
        __syncthreads();
        float acc[2][4] = {{0.f,0.f,0.f,0.f},{0.f,0.f,0.f,0.f}};
        for (int k = 0; k < 128; k++) {
            float a0 = sT[(ty*2)*128 + k];
            float a1 = sT[(ty*2 + 1)*128 + k];
            float bb[4];
            #pragma unroll
            for (int j = 0; j < 4; j++) bb[j] = sW[k*32 + tx*4 + j];
            #pragma unroll
            for (int j = 0; j < 4; j++) {
                acc[0][j] = fmaf(a0, bb[j], acc[0][j]);
                acc[1][j] = fmaf(a1, bb[j], acc[1][j]);
            }
        }
        float* outl = pass ? g_xls : g_xl2;
        float* outr = pass ? g_xrs : g_xr2;
        #pragma unroll
        for (int i = 0; i < 2; i++) {
            int n = n0 + ty*2 + i;
            if (n < NN) {
                #pragma unroll
                for (int j = 0; j < 4; j++) {
                    int c = tx*4 + j;
                    if (c < 16) outl[(b*NN + n)*16 + c]      = acc[i][j];
                    else        outr[(b*NN + n)*16 + c - 16] = acc[i][j];
                }
            }
        }
    }
}

// ------- conv2 + skip + lin + layernorm fused; depth-2 pipeline -------
__global__ void __launch_bounds__(256, 2) conv2_kernel(const float* __restrict__ ea,
                                                       const float* __restrict__ c2We,
                                                       const float* __restrict__ c2att,
                                                       const float* __restrict__ c2b,
                                                       const float* __restrict__ sWe,
                                                       const float* __restrict__ satt,
                                                       const float* __restrict__ sb,
                                                       const float* __restrict__ linW,
                                                       const float* __restrict__ linb,
                                                       const float* __restrict__ lng,
                                                       const float* __restrict__ lnb,
                                                       float* __restrict__ out) {
    int b = blockIdx.y;
    int n = blockIdx.x * 8 + (threadIdx.x >> 5);
    if (n >= NN) return;
    int lane = threadIdx.x & 31;
    int half = lane >> 4;
    int c = lane & 15;

    const float* xlbase = half ? g_xls : g_xl2;
    float xr   = (half ? g_xrs : g_xr2)[(size_t)(b*NN + n)*16 + c];
    float attv = (half ? satt : c2att)[c];
    float Wc[16];
    const float* Wmat = half ? sWe : c2We;
    #pragma unroll
    for (int k = 0; k < 16; k++) Wc[k] = Wmat[k*16 + c];

    const int*   elist = g_elist + b*EE;
    const int*   slist = g_slist + b*EE;
    const float* eab   = ea + (size_t)b*EE*EDD;
    int start = g_offsets[b*(NN+1) + n];
    int end   = g_offsets[b*(NN+1) + n + 1];

    float acc = 0.f, den = 0.f;

    auto body = [&](float xl, float eav) {
        float u = xl + xr;
        #pragma unroll
        for (int k = 0; k < 16; k++)
            u = fmaf(__shfl_sync(0xffffffffu, eav, k, 16), Wc[k], u);
        u = fmaxf(u, 0.f) + 0.2f * fminf(u, 0.f);
        float s = u * attv;
        s += __shfl_xor_sync(0xffffffffu, s, 1);
        s += __shfl_xor_sync(0xffffffffu, s, 2);
        s += __shfl_xor_sync(0xffffffffu, s, 4);
        s += __shfl_xor_sync(0xffffffffu, s, 8);
        float exs = __expf(s);
        den += exs;
        acc = fmaf(xl, exs, acc);
    };

    float xl0 = 0.f, xl1 = 0.f, ea0 = 0.f, ea1 = 0.f;
    int e2 = 0, s2 = 0, e3 = 0, s3 = 0;
    if (start < end) {
        int e = elist[start], s = slist[start];
        ea0 = eab[(size_t)e*EDD + c];
        xl0 = xlbase[(size_t)(b*NN + s)*16 + c];
    }
    if (start + 1 < end) {
        int e = elist[start+1], s = slist[start+1];
        ea1 = eab[(size_t)e*EDD + c];
        xl1 = xlbase[(size_t)(b*NN + s)*16 + c];
    }
    if (start + 2 < end) { e2 = elist[start+2]; s2 = slist[start+2]; }
    if (start + 3 < end) { e3 = elist[start+3]; s3 = slist[start+3]; }

    for (int i = start; i < end; i += 2) {
        float xlc = xl0, eac = ea0;
        if (i + 2 < end) {
            ea0 = eab[(size_t)e2*EDD + c];
            xl0 = xlbase[(size_t)(b*NN + s2)*16 + c];
        }
        if (i + 4 < end) { e2 = elist[i+4]; s2 = slist[i+4]; }
        body(xlc, eac);
        if (i + 1 < end) {
            float xld = xl1, ead = ea1;
            if (i + 3 < end) {
                ea1 = eab[(size_t)e3*EDD + c];
                xl1 = xlbase[(size_t)(b*NN + s3)*16 + c];
            }
            if (i + 5 < end) { e3 = elist[i+5]; s3 = slist[i+5]; }
            body(xld, ead);
        }
    }

    float v = acc / (den + 1e-16f) + (half ? sb[c] : c2b[c]);

    float t = 0.f;
    #pragma unroll
    for (int k = 0; k < 16; k++) {
        float vk = __shfl_sync(0xffffffffu, v, k, 16);
        t = fmaf(vk, linW[c*16 + k], t);
    }
    float part  = half ? (t + linb[c]) : v;
    float other = __shfl_xor_sync(0xffffffffu, part, 16);
    float y = part + other;

    float mu = y;
    mu += __shfl_xor_sync(0xffffffffu, mu, 1);
    mu += __shfl_xor_sync(0xffffffffu, mu, 2);
    mu += __shfl_xor_sync(0xffffffffu, mu, 4);
    mu += __shfl_xor_sync(0xffffffffu, mu, 8);
    mu *= (1.f / 16.f);
    float d = y - mu;
    float var = d * d;
    var += __shfl_xor_sync(0xffffffffu, var, 1);
    var += __shfl_xor_sync(0xffffffffu, var, 2);
    var += __shfl_xor_sync(0xffffffffu, var, 4);
    var += __shfl_xor_sync(0xffffffffu, var, 8);
    var *= (1.f / 16.f);
    float o = d * rsqrtf(var + 1e-5f) * lng[c] + lnb[c];
    if (!half) out[(size_t)(b*NN + n)*16 + c] = o;
}

// ---------------- launch ----------------
extern "C" void kernel_launch(void* const* d_in, const int* in_sizes, int n_in,
                              void* d_out, int out_size) {
    const float* x      = (const float*)d_in[0];
    const float* ea     = (const float*)d_in[1];
    const int*   ei     = (const int*)  d_in[2];
    const float* c1_Wl  = (const float*)d_in[3];
    const float* c1_Wr  = (const float*)d_in[4];
    const float* c1_We  = (const float*)d_in[5];
    const float* c1_att = (const float*)d_in[6];
    const float* c1_b   = (const float*)d_in[7];
    const float* c2_Wl  = (const float*)d_in[8];
    const float* c2_Wr  = (const float*)d_in[9];
    const float* c2_We  = (const float*)d_in[10];
    const float* c2_att = (const float*)d_in[11];
    const float* c2_b   = (const float*)d_in[12];
    const float* s_Wl   = (const float*)d_in[13];
    const float* s_Wr   = (const float*)d_in[14];
    const float* s_We   = (const float*)d_in[15];
    const float* s_att  = (const float*)d_in[16];
    const float* s_b    = (const float*)d_in[17];
    const float* lin_W  = (const float*)d_in[18];
    const float* lin_b  = (const float*)d_in[19];
    const float* ln_g   = (const float*)d_in[20];
    const float* ln_b   = (const float*)d_in[21];
    float* out = (float*)d_out;

    zero_kernel   <<<(BB*NN + 255)/256, 256>>>();
    count_kernel  <<<(BB*EE + 255)/256, 256>>>(ei);
    scan_kernel   <<<BB, 1024>>>();
    scatter_kernel<<<(BB*EE + 255)/256, 256>>>(ei);

    gemm1_kernel<<<dim3((NN + 63)/64, BB), 256>>>(x, c1_Wl, c1_Wr);
    conv1_kernel<<<dim3((NN + 7)/8,  BB), 256>>>(ea, c1_We, c1_att, c1_b);
    gemm2_kernel<<<dim3((NN + 63)/64, BB), 256>>>(c2_Wl, c2_Wr, s_Wl, s_Wr);
    conv2_kernel<<<dim3((NN + 7)/8,  BB), 256>>>(ea, c2_We, c2_att, c2_b,
                                                 s_We, s_att, s_b,
                                                 lin_W, lin_b, ln_g, ln_b, out);
}

// round 9
// speedup vs baseline: 1.8242x; 1.0254x over previous
#include <cuda_runtime.h>
#include <math.h>

#define BB  4
#define NN  20000
#define EE  640000
#define FF  64
#define EDD 16
#define D1  128
#define HIDC 16

typedef unsigned long long ull;

__device__ __forceinline__ ull fma2(ull a, ull b, ull c) {
    ull d; asm("fma.rn.f32x2 %0, %1, %2, %3;" : "=l"(d) : "l"(a), "l"(b), "l"(c)); return d;
}
__device__ __forceinline__ ull add2(ull a, ull b) {
    ull d; asm("add.rn.f32x2 %0, %1, %2;" : "=l"(d) : "l"(a), "l"(b)); return d;
}
__device__ __forceinline__ ull dup2(float a) {
    ull d; asm("mov.b64 %0, {%1, %1};" : "=l"(d) : "r"(__float_as_uint(a))); return d;
}
union F4U { float4 f; ulonglong2 u; };

// ---------------- device scratch (no cudaMalloc allowed) ----------------
__device__ int   g_count [BB*NN];
__device__ int   g_cursor[BB*NN];
__device__ int   g_offsets[BB*(NN+1)];
__device__ int   g_elist [BB*EE];
__device__ int   g_slist [BB*EE];
__device__ float g_xl1[BB*NN*D1];
__device__ float g_xr1[BB*NN*D1];
__device__ float g_hx [BB*NN*D1];
__device__ float g_hs [BB*NN*D1];
__device__ float g_xl2[BB*NN*HIDC];
__device__ float g_xr2[BB*NN*HIDC];
__device__ float g_xls[BB*NN*HIDC];
__device__ float g_xrs[BB*NN*HIDC];

// ---------------- CSR build ----------------
__global__ void zero_kernel() {
    int i = blockIdx.x * blockDim.x + threadIdx.x;
    if (i < BB*NN) { g_count[i] = 0; g_cursor[i] = 0; }
}

__global__ void count_kernel(const int* __restrict__ ei) {
    int i = blockIdx.x * blockDim.x + threadIdx.x;
    if (i >= BB*EE) return;
    int b = i / EE, e = i - b*EE;
    int dst = ei[b*2*EE + EE + e];
    atomicAdd(&g_count[b*NN + dst], 1);
}

// warp-scan based block scan: 3 barriers per 1024-chunk
__global__ void scan_kernel() {
    __shared__ int warpsum[32];
    __shared__ int chunkoff;
    int b = blockIdx.x, tid = threadIdx.x;
    int lane = tid & 31, wid = tid >> 5;
    if (tid == 0) chunkoff = 0;
    __syncthreads();
    for (int base = 0; base < NN; base += 1024) {
        int i = base + tid;
        int v = (i < NN) ? g_count[b*NN + i] : 0;
        int s = v;
        #pragma unroll
        for (int off = 1; off < 32; off <<= 1) {
            int t = __shfl_up_sync(0xffffffffu, s, off);
            if (lane >= off) s += t;
        }
        if (lane == 31) warpsum[wid] = s;
        __syncthreads();
        if (wid == 0) {
            int ws = warpsum[lane];
            #pragma unroll
            for (int off = 1; off < 32; off <<= 1) {
                int t = __shfl_up_sync(0xffffffffu, ws, off);
                if (lane >= off) ws += t;
            }
            warpsum[lane] = ws;
        }
        __syncthreads();
        int prefix = chunkoff + (wid > 0 ? warpsum[wid-1] : 0) + s - v;  // exclusive
        if (i < NN) g_offsets[b*(NN+1) + i] = prefix;
        __syncthreads();
        if (tid == 0) chunkoff += warpsum[31];
        __syncthreads();
    }
    if (threadIdx.x == 0) g_offsets[b*(NN+1) + NN] = chunkoff;
}

__global__ void scatter_kernel(const int* __restrict__ ei) {
    int i = blockIdx.x * blockDim.x + threadIdx.x;
    if (i >= BB*EE) return;
    int b = i / EE, e = i - b*EE;
    int src = ei[b*2*EE + e];
    int dst = ei[b*2*EE + EE + e];
    int pos = atomicAdd(&g_cursor[b*NN + dst], 1);
    int slot = b*EE + g_offsets[b*(NN+1) + dst] + pos;
    g_elist[slot] = e;
    g_slist[slot] = src;
}

// ---------------- GEMM 1: xl1 = x@Wl1, xr1 = x@Wr1 ----------------
__global__ void __launch_bounds__(256) gemm1_kernel(const float* __restrict__ x,
                                                    const float* __restrict__ Wl,
                                                    const float* __restrict__ Wr) {
    __shared__ float sX[64*64];
    __shared__ float sW[64*128];
    int b = blockIdx.y, n0 = blockIdx.x * 64, tid = threadIdx.x;

    for (int t = tid; t < 64*64; t += 256) {
        int r = t >> 6, c = t & 63;
        int n = n0 + r;
        sX[t] = (n < NN) ? x[(b*NN + n)*FF + c] : 0.f;
    }
    int ty = tid >> 4, tx = tid & 15;
    for (int pass = 0; pass < 2; ++pass) {
        const float* W = pass ? Wr : Wl;
        __syncthreads();
        for (int t = tid; t < 64*128; t += 256) sW[t] = W[t];
        __syncthreads();
        float acc[4][8];
        #pragma unroll
        for (int i = 0; i < 4; i++)
            #pragma unroll
            for (int j = 0; j < 8; j++) acc[i][j] = 0.f;
        for (int k = 0; k < 64; k += 4) {
            float4 a4[4];
            #pragma unroll
            for (int i = 0; i < 4; i++)
                a4[i] = *(const float4*)&sX[(ty*4 + i)*64 + k];
            #pragma unroll
            for (int kk = 0; kk < 4; kk++) {
                float bb[8];
                #pragma unroll
                for (int j = 0; j < 8; j++) bb[j] = sW[(k+kk)*128 + tx*8 + j];
                #pragma unroll
                for (int i = 0; i < 4; i++) {
                    float a = (kk == 0) ? a4[i].x : (kk == 1) ? a4[i].y : (kk == 2) ? a4[i].z : a4[i].w;
                    #pragma unroll
                    for (int j = 0; j < 8; j++) acc[i][j] = fmaf(a, bb[j], acc[i][j]);
                }
            }
        }
        float* out = pass ? g_xr1 : g_xl1;
        #pragma unroll
        for (int i = 0; i < 4; i++) {
            int n = n0 + ty*4 + i;
            if (n < NN) {
                #pragma unroll
                for (int j = 0; j < 8; j++)
                    out[(b*NN + n)*128 + tx*8 + j] = acc[i][j];
            }
        }
    }
}

// ------- conv1: warp/node, depth-2 pipeline, FFMA2 via register dup -------
__global__ void __launch_bounds__(256, 2) conv1_kernel(const float* __restrict__ ea,
                                                       const float* __restrict__ We,
                                                       const float* __restrict__ att,
                                                       const float* __restrict__ bias) {
    int b = blockIdx.y;
    int n = blockIdx.x * 8 + (threadIdx.x >> 5);
    if (n >= NN) return;
    int lane = threadIdx.x & 31;
    int cb = 4 * lane;
    int lx = lane & 15;
    int row = b*NN + n;

    F4U xr; xr.f = *(const float4*)(g_xr1 + (size_t)row*128 + cb);
    float4 at4 = *(const float4*)(att + cb);
    ull WeA[16], WeB[16];
    #pragma unroll
    for (int k = 0; k < 16; k++) {
        F4U t; t.f = *(const float4*)(We + k*128 + cb);
        WeA[k] = t.u.x; WeB[k] = t.u.y;
    }

    const int*   elist = g_elist + b*EE;
    const int*   slist = g_slist + b*EE;
    const float* eab   = ea + (size_t)b*EE*EDD;
    int start = g_offsets[b*(NN+1) + n];
    int end   = g_offsets[b*(NN+1) + n + 1];

    ull accA = 0ull, accB = 0ull;
    float den = 0.f;

    auto body = [&](F4U xl, float eav) {
        ull uA = add2(xl.u.x, xr.u.x);
        ull uB = add2(xl.u.y, xr.u.y);
        #pragma unroll
        for (int k = 0; k < 16; k++) {
            float a = __shfl_sync(0xffffffffu, eav, k, 16);
            ull a2 = dup2(a);
            uA = fma2(a2, WeA[k], uA);
            uB = fma2(a2, WeB[k], uB);
        }
        F4U uu; uu.u.x = uA; uu.u.y = uB;
        float u0 = uu.f.x, u1 = uu.f.y, u2 = uu.f.z, u3 = uu.f.w;
        u0 = fmaxf(u0, 0.f) + 0.2f * fminf(u0, 0.f);
        u1 = fmaxf(u1, 0.f) + 0.2f * fminf(u1, 0.f);
        u2 = fmaxf(u2, 0.f) + 0.2f * fminf(u2, 0.f);
        u3 = fmaxf(u3, 0.f) + 0.2f * fminf(u3, 0.f);
        float s = fmaf(u0, at4.x, fmaf(u1, at4.y, fmaf(u2, at4.z, u3 * at4.w)));
        s += __shfl_xor_sync(0xffffffffu, s, 1);
        s += __shfl_xor_sync(0xffffffffu, s, 2);
        float exs = __expf(s);
        den += exs;
        ull e2p = dup2(exs);
        accA = fma2(xl.u.x, e2p, accA);
        accB = fma2(xl.u.y, e2p, accB);
    };

    // depth-2 pipeline: data for i,i+1 resident; indices for i+2,i+3 resident
    F4U xl0, xl1;
    xl0.f = make_float4(0.f,0.f,0.f,0.f); xl1 = xl0;
    float ea0 = 0.f, ea1 = 0.f;
    int e2 = 0, s2 = 0, e3 = 0, s3 = 0;
    if (start < end) {
        int e = elist[start], s = slist[start];
        ea0 = eab[(size_t)e*EDD + lx];
        xl0.f = *(const float4*)(g_xl1 + (size_t)(b*NN + s)*128 + cb);
    }
    if (start + 1 < end) {
        int e = elist[start+1], s = slist[start+1];
        ea1 = eab[(size_t)e*EDD + lx];
        xl1.f = *(const float4*)(g_xl1 + (size_t)(b*NN + s)*128 + cb);
    }
    if (start + 2 < end) { e2 = elist[start+2]; s2 = slist[start+2]; }
    if (start + 3 < end) { e3 = elist[start+3]; s3 = slist[start+3]; }

    for (int i = start; i < end; i += 2) {
        F4U xlc = xl0; float eac = ea0;
        if (i + 2 < end) {
            ea0 = eab[(size_t)e2*EDD + lx];
            xl0.f = *(const float4*)(g_xl1 + (size_t)(b*NN + s2)*128 + cb);
        }
        if (i + 4 < end) { e2 = elist[i+4]; s2 = slist[i+4]; }
        body(xlc, eac);
        if (i + 1 < end) {
            F4U xld = xl1; float ead = ea1;
            if (i + 3 < end) {
                ea1 = eab[(size_t)e3*EDD + lx];
                xl1.f = *(const float4*)(g_xl1 + (size_t)(b*NN + s3)*128 + cb);
            }
            if (i + 5 < end) { e3 = elist[i+5]; s3 = slist[i+5]; }
            body(xld, ead);
        }
    }

    F4U accu; accu.u.x = accA; accu.u.y = accB;
    float inv = 1.f / (den + 1e-16f);
    float4 b4 = *(const float4*)(bias + cb);
    float h0 = fmaf(accu.f.x, inv, b4.x);
    float h1 = fmaf(accu.f.y, inv, b4.y);
    float h2 = fmaf(accu.f.z, inv, b4.z);
    float h3 = fmaf(accu.f.w, inv, b4.w);
    float o0 = h0 > 0.f ? h0 : expm1f(h0);
    float o1 = h1 > 0.f ? h1 : expm1f(h1);
    float o2 = h2 > 0.f ? h2 : expm1f(h2);
    float o3 = h3 > 0.f ? h3 : expm1f(h3);
    float4 sk = *(const float4*)(g_xl1 + (size_t)row*128 + cb);
    *(float4*)(g_hx + (size_t)row*128 + cb) = make_float4(o0, o1, o2, o3);
    *(float4*)(g_hs + (size_t)row*128 + cb) = make_float4(o0 + sk.x, o1 + sk.y, o2 + sk.z, o3 + sk.w);
}

// ---------------- GEMM 2: four [N,128]@[128,16] projections ----------------
__global__ void __launch_bounds__(256) gemm2_kernel(const float* __restrict__ c2Wl,
                                                    const float* __restrict__ c2Wr,
                                                    const float* __restrict__ sWl,
                                                    const float* __restrict__ sWr) {
    __shared__ float sT[64*128];
    __shared__ float sW[128*32];
    int b = blockIdx.y, n0 = blockIdx.x * 64, tid = threadIdx.x;
    int ty = tid >> 3, tx = tid & 7;

    for (int pass = 0; pass < 2; ++pass) {
        const float* inp = pass ? g_hs : g_hx;
        const float* Wl  = pass ? sWl  : c2Wl;
        const float* Wr  = pass ? sWr  : c2Wr;
        __syncthreads();
        for (int t = tid; t < 64*128; t += 256) {
            int r = t >> 7, c = t & 127;
            int n = n0 + r;
            sT[t] = (n < NN) ? inp[(b*NN + n)*128 + c] : 0.f;
        }
        for (int t = tid; t < 128*16; t += 256) {
            int r = t >> 4, c = t & 15;
            sW[r*32 + c]      = Wl[t];
            sW[r*32 + 16 + c] = Wr[t];
        }
        __syncthreads();
        float acc[2][4] = {{0.f,0.f,0.f,0.f},{0.f,0.f,0.f,0.f}};
        for (int k = 0; k < 128; k++) {
            float a0 = sT[(ty*2)*128 + k];
            float a1 = sT[(ty*2 + 1)*128 + k];
            float bb[4];
            #pragma unroll
            for (int j = 0; j < 4; j++) bb[j] = sW[k*32 + tx*4 + j];
            #pragma unroll
            for (int j = 0; j < 4; j++) {
                acc[0][j] = fmaf(a0, bb[j], acc[0][j]);
                acc[1][j] = fmaf(a1, bb[j], acc[1][j]);
            }
        }
        float* outl = pass ? g_xls : g_xl2;
        float* outr = pass ? g_xrs : g_xr2;
        #pragma unroll
        for (int i = 0; i < 2; i++) {
            int n = n0 + ty*2 + i;
            if (n < NN) {
                #pragma unroll
                for (int j = 0; j < 4; j++) {
                    int c = tx*4 + j;
                    if (c < 16) outl[(b*NN + n)*16 + c]      = acc[i][j];
                    else        outr[(b*NN + n)*16 + c - 16] = acc[i][j];
                }
            }
        }
    }
}

// ------- conv2 + skip + lin + layernorm fused; depth-2 pipeline -------
__global__ void __launch_bounds__(256, 2) conv2_kernel(const float* __restrict__ ea,
                                                       const float* __restrict__ c2We,
                                                       const float* __restrict__ c2att,
                                                       const float* __restrict__ c2b,
                                                       const float* __restrict__ sWe,
                                                       const float* __restrict__ satt,
                                                       const float* __restrict__ sb,
                                                       const float* __restrict__ linW,
                                                       const float* __restrict__ linb,
                                                       const float* __restrict__ lng,
                                                       const float* __restrict__ lnb,
                                                       float* __restrict__ out) {
    int b = blockIdx.y;
    int n = blockIdx.x * 8 + (threadIdx.x >> 5);
    if (n >= NN) return;
    int lane = threadIdx.x & 31;
    int half = lane >> 4;
    int c = lane & 15;

    const float* xlbase = half ? g_xls : g_xl2;
    float xr   = (half ? g_xrs : g_xr2)[(size_t)(b*NN + n)*16 + c];
    float attv = (half ? satt : c2att)[c];
    float Wc[16];
    const float* Wmat = half ? sWe : c2We;
    #pragma unroll
    for (int k = 0; k < 16; k++) Wc[k] = Wmat[k*16 + c];

    const int*   elist = g_elist + b*EE;
    const int*   slist = g_slist + b*EE;
    const float* eab   = ea + (size_t)b*EE*EDD;
    int start = g_offsets[b*(NN+1) + n];
    int end   = g_offsets[b*(NN+1) + n + 1];

    float acc = 0.f, den = 0.f;

    auto body = [&](float xl, float eav) {
        float u = xl + xr;
        #pragma unroll
        for (int k = 0; k < 16; k++)
            u = fmaf(__shfl_sync(0xffffffffu, eav, k, 16), Wc[k], u);
        u = fmaxf(u, 0.f) + 0.2f * fminf(u, 0.f);
        float s = u * attv;
        s += __shfl_xor_sync(0xffffffffu, s, 1);
        s += __shfl_xor_sync(0xffffffffu, s, 2);
        s += __shfl_xor_sync(0xffffffffu, s, 4);
        s += __shfl_xor_sync(0xffffffffu, s, 8);
        float exs = __expf(s);
        den += exs;
        acc = fmaf(xl, exs, acc);
    };

    float xl0 = 0.f, xl1 = 0.f, ea0 = 0.f, ea1 = 0.f;
    int e2 = 0, s2 = 0, e3 = 0, s3 = 0;
    if (start < end) {
        int e = elist[start], s = slist[start];
        ea0 = eab[(size_t)e*EDD + c];
        xl0 = xlbase[(size_t)(b*NN + s)*16 + c];
    }
    if (start + 1 < end) {
        int e = elist[start+1], s = slist[start+1];
        ea1 = eab[(size_t)e*EDD + c];
        xl1 = xlbase[(size_t)(b*NN + s)*16 + c];
    }
    if (start + 2 < end) { e2 = elist[start+2]; s2 = slist[start+2]; }
    if (start + 3 < end) { e3 = elist[start+3]; s3 = slist[start+3]; }

    for (int i = start; i < end; i += 2) {
        float xlc = xl0, eac = ea0;
        if (i + 2 < end) {
            ea0 = eab[(size_t)e2*EDD + c];
            xl0 = xlbase[(size_t)(b*NN + s2)*16 + c];
        }
        if (i + 4 < end) { e2 = elist[i+4]; s2 = slist[i+4]; }
        body(xlc, eac);
        if (i + 1 < end) {
            float xld = xl1, ead = ea1;
            if (i + 3 < end) {
                ea1 = eab[(size_t)e3*EDD + c];
                xl1 = xlbase[(size_t)(b*NN + s3)*16 + c];
            }
            if (i + 5 < end) { e3 = elist[i+5]; s3 = slist[i+5]; }
            body(xld, ead);
        }
    }

    float v = acc / (den + 1e-16f) + (half ? sb[c] : c2b[c]);

    float t = 0.f;
    #pragma unroll
    for (int k = 0; k < 16; k++) {
        float vk = __shfl_sync(0xffffffffu, v, k, 16);
        t = fmaf(vk, linW[c*16 + k], t);
    }
    float part  = half ? (t + linb[c]) : v;
    float other = __shfl_xor_sync(0xffffffffu, part, 16);
    float y = part + other;

    float mu = y;
    mu += __shfl_xor_sync(0xffffffffu, mu, 1);
    mu += __shfl_xor_sync(0xffffffffu, mu, 2);
    mu += __shfl_xor_sync(0xffffffffu, mu, 4);
    mu += __shfl_xor_sync(0xffffffffu, mu, 8);
    mu *= (1.f / 16.f);
    float d = y - mu;
    float var = d * d;
    var += __shfl_xor_sync(0xffffffffu, var, 1);
    var += __shfl_xor_sync(0xffffffffu, var, 2);
    var += __shfl_xor_sync(0xffffffffu, var, 4);
    var += __shfl_xor_sync(0xffffffffu, var, 8);
    var *= (1.f / 16.f);
    float o = d * rsqrtf(var + 1e-5f) * lng[c] + lnb[c];
    if (!half) out[(size_t)(b*NN + n)*16 + c] = o;
}

// ---------------- launch ----------------
extern "C" void kernel_launch(void* const* d_in, const int* in_sizes, int n_in,
                              void* d_out, int out_size) {
    const float* x      = (const float*)d_in[0];
    const float* ea     = (const float*)d_in[1];
    const int*   ei     = (const int*)  d_in[2];
    const float* c1_Wl  = (const float*)d_in[3];
    const float* c1_Wr  = (const float*)d_in[4];
    const float* c1_We  = (const float*)d_in[5];
    const float* c1_att = (const float*)d_in[6];
    const float* c1_b   = (const float*)d_in[7];
    const float* c2_Wl  = (const float*)d_in[8];
    const float* c2_Wr  = (const float*)d_in[9];
    const float* c2_We  = (const float*)d_in[10];
    const float* c2_att = (const float*)d_in[11];
    const float* c2_b   = (const float*)d_in[12];
    const float* s_Wl   = (const float*)d_in[13];
    const float* s_Wr   = (const float*)d_in[14];
    const float* s_We   = (const float*)d_in[15];
    const float* s_att  = (const float*)d_in[16];
    const float* s_b    = (const float*)d_in[17];
    const float* lin_W  = (const float*)d_in[18];
    const float* lin_b  = (const float*)d_in[19];
    const float* ln_g   = (const float*)d_in[20];
    const float* ln_b   = (const float*)d_in[21];
    float* out = (float*)d_out;

    zero_kernel   <<<(BB*NN + 255)/256, 256>>>();
    count_kernel  <<<(BB*EE + 255)/256, 256>>>(ei);
    scan_kernel   <<<BB, 1024>>>();
    scatter_kernel<<<(BB*EE + 255)/256, 256>>>(ei);

    gemm1_kernel<<<dim3((NN + 63)/64, BB), 256>>>(x, c1_Wl, c1_Wr);
    conv1_kernel<<<dim3((NN + 7)/8,  BB), 256>>>(ea, c1_We, c1_att, c1_b);
    gemm2_kernel<<<dim3((NN + 63)/64, BB), 256>>>(c2_Wl, c2_Wr, s_Wl, s_Wr);
    conv2_kernel<<<dim3((NN + 7)/8,  BB), 256>>>(ea, c2_We, c2_att, c2_b,
                                                 s_We, s_att, s_b,
                                                 lin_W, lin_b, ln_g, ln_b, out);
}